// round 7
// baseline (speedup 1.0000x reference)
#include <cuda_runtime.h>
#include <cuda_bf16.h>
#include <math.h>
#include <stdint.h>

#define HEADS 12
#define SEQ   2048
#define DIM   64
#define EMB   768
#define BATCH 4
#define MROWS (BATCH*SEQ)   // 8192

// ---------------- scratch (static device globals; no allocation) ----------
__device__ float g_AO[MROWS*EMB];            // attention out, [B*S, 768]

__device__ __nv_bfloat16 g_Qh[BATCH*HEADS*SEQ*DIM];
__device__ __nv_bfloat16 g_Ql[BATCH*HEADS*SEQ*DIM];
__device__ __nv_bfloat16 g_Kh[BATCH*HEADS*SEQ*DIM];
__device__ __nv_bfloat16 g_Kl[BATCH*HEADS*SEQ*DIM];
__device__ __nv_bfloat16 g_Vh[BATCH*HEADS*SEQ*DIM];
__device__ __nv_bfloat16 g_Vl[BATCH*HEADS*SEQ*DIM];

__device__ __nv_bfloat16 g_v1h[MROWS*EMB];
__device__ __nv_bfloat16 g_v1l[MROWS*EMB];
__device__ __nv_bfloat16 g_v2h[MROWS*EMB];
__device__ __nv_bfloat16 g_v2l[MROWS*EMB];
__device__ __nv_bfloat16 g_Wh[4*EMB*EMB];    // slots: 0=q 1=k 2=v 3=o
__device__ __nv_bfloat16 g_Wl[4*EMB*EMB];

// ---------------- helpers --------------------------------------------------
__device__ __forceinline__ uint32_t smem_u32(const void* p) {
    uint32_t a;
    asm("{ .reg .u64 t; cvta.to.shared.u64 t, %1; cvt.u32.u64 %0, t; }"
        : "=r"(a) : "l"(p));
    return a;
}
__device__ __forceinline__ void mma16816(float* c, const uint32_t* a,
                                         uint32_t b0, uint32_t b1) {
    asm volatile(
        "mma.sync.aligned.m16n8k16.row.col.f32.bf16.bf16.f32 "
        "{%0,%1,%2,%3}, {%4,%5,%6,%7}, {%8,%9}, {%0,%1,%2,%3};"
        : "+f"(c[0]), "+f"(c[1]), "+f"(c[2]), "+f"(c[3])
        : "r"(a[0]), "r"(a[1]), "r"(a[2]), "r"(a[3]), "r"(b0), "r"(b1));
}
__device__ __forceinline__ void ldm_x4(uint32_t* r, uint32_t addr) {
    asm volatile("ldmatrix.sync.aligned.m8n8.x4.shared.b16 {%0,%1,%2,%3}, [%4];"
                 : "=r"(r[0]), "=r"(r[1]), "=r"(r[2]), "=r"(r[3]) : "r"(addr));
}
__device__ __forceinline__ void ldm_x4t(uint32_t* r, uint32_t addr) {
    asm volatile("ldmatrix.sync.aligned.m8n8.x4.trans.shared.b16 {%0,%1,%2,%3}, [%4];"
                 : "=r"(r[0]), "=r"(r[1]), "=r"(r[2]), "=r"(r[3]) : "r"(addr));
}
#define CP_A16(dst, src) \
    asm volatile("cp.async.cg.shared.global [%0], [%1], 16;" :: "r"(dst), "l"(src))
#define CP_COMMIT() asm volatile("cp.async.commit_group;" ::: "memory")
#define CP_WAIT1()  asm volatile("cp.async.wait_group 1;" ::: "memory")
#define CP_WAIT0()  asm volatile("cp.async.wait_group 0;" ::: "memory")

__device__ __forceinline__ uint32_t packbf(float lo, float hi) {
    __nv_bfloat162 t = __floats2bfloat162_rn(lo, hi);
    return *(uint32_t*)&t;
}
__device__ __forceinline__ void splitpair(float v0, float v1,
                                          uint32_t& hi, uint32_t& lo) {
    float h0 = __bfloat162float(__float2bfloat16_rn(v0));
    float h1 = __bfloat162float(__float2bfloat16_rn(v1));
    hi = packbf(h0, h1);
    lo = packbf(v0 - h0, v1 - h1);
}

// ---------------- split-bf16 conversion -----------------------------------
__global__ void __launch_bounds__(256)
cvt_split(const float* __restrict__ in, __nv_bfloat16* __restrict__ hi,
          __nv_bfloat16* __restrict__ lo, int n4)
{
    int i = blockIdx.x * blockDim.x + threadIdx.x;
    if (i >= n4) return;
    float4 v = ((const float4*)in)[i];
    uint32_t h01, l01, h23, l23;
    splitpair(v.x, v.y, h01, l01);
    splitpair(v.z, v.w, h23, l23);
    ((uint2*)hi)[i] = make_uint2(h01, h23);
    ((uint2*)lo)[i] = make_uint2(l01, l23);
}
__global__ void __launch_bounds__(256)
cvt_split_w(const float* __restrict__ w0, const float* __restrict__ w1,
            const float* __restrict__ w2, const float* __restrict__ w3,
            __nv_bfloat16* __restrict__ hi, __nv_bfloat16* __restrict__ lo, int n4)
{
    int i = blockIdx.x * blockDim.x + threadIdx.x;
    if (i >= n4) return;
    int s = blockIdx.y;
    const float* in = (s == 0) ? w0 : (s == 1) ? w1 : (s == 2) ? w2 : w3;
    float4 v = ((const float4*)in)[i];
    uint32_t h01, l01, h23, l23;
    splitpair(v.x, v.y, h01, l01);
    splitpair(v.z, v.w, h23, l23);
    size_t off = (size_t)s * (EMB * EMB / 4) + i;
    ((uint2*)hi)[off] = make_uint2(h01, h23);
    ((uint2*)lo)[off] = make_uint2(l01, l23);
}

// ---------------- shared GEMM mainloop (cp.async 2-stage, K-tile 16) -------
#define GKT  16
#define GPAD 24
#define GTEN (128*GPAD)
#define GSTG (4*GTEN)

__device__ __forceinline__ void gemm_mainloop(
    const __nv_bfloat16* __restrict__ Ah, const __nv_bfloat16* __restrict__ Al,
    const __nv_bfloat16* __restrict__ Wh, const __nv_bfloat16* __restrict__ Wl,
    int m0, int n0, uint32_t sb, int tid, int lane, int wm, int wn,
    float (&acc)[2][8][4])
{
    const __nv_bfloat16* srcs[4] = {Ah, Al, Wh, Wl};
    const int rb[4] = {m0, m0, n0, n0};

    auto prefetch = [&](int kt, int st) {
#pragma unroll
        for (int u = 0; u < 4; u++) {
            int idx  = tid + u * 256;
            int tile = idx >> 8;
            int r    = (idx >> 1) & 127;
            int c    = idx & 1;
            uint32_t dst = sb + (uint32_t)(st * GSTG + tile * GTEN + r * GPAD + c * 8) * 2;
            CP_A16(dst, srcs[tile] + (size_t)(rb[tile] + r) * EMB + kt * GKT + c * 8);
        }
        CP_COMMIT();
    };

    prefetch(0, 0);
    const int NKT = EMB / GKT;   // 48
    for (int kt = 0; kt < NKT; kt++) {
        const int st = kt & 1;
        if (kt + 1 < NKT) { prefetch(kt + 1, st ^ 1); CP_WAIT1(); }
        else              { CP_WAIT0(); }
        __syncthreads();

        const uint32_t so = sb + (uint32_t)(st * GSTG) * 2;
        uint32_t ah[2][4], al_[2][4];
#pragma unroll
        for (int i = 0; i < 2; i++) {
            int row  = wm * 32 + i * 16 + (lane & 15);
            int colh = (lane >> 4) << 3;
            ldm_x4(ah[i],  so + (uint32_t)(0 * GTEN + row * GPAD + colh) * 2);
            ldm_x4(al_[i], so + (uint32_t)(1 * GTEN + row * GPAD + colh) * 2);
        }
#pragma unroll
        for (int jp = 0; jp < 4; jp++) {
            int row  = wn * 64 + jp * 16 + ((lane >> 4) << 3) + (lane & 7);
            int colh = ((lane >> 3) & 1) << 3;
            uint32_t bh4[4], bl4[4];
            ldm_x4(bh4, so + (uint32_t)(2 * GTEN + row * GPAD + colh) * 2);
            ldm_x4(bl4, so + (uint32_t)(3 * GTEN + row * GPAD + colh) * 2);
            // interleave: 4 independent accumulators per term (dep distance 4)
            mma16816(acc[0][2*jp],   ah[0],  bh4[0], bh4[1]);
            mma16816(acc[1][2*jp],   ah[1],  bh4[0], bh4[1]);
            mma16816(acc[0][2*jp+1], ah[0],  bh4[2], bh4[3]);
            mma16816(acc[1][2*jp+1], ah[1],  bh4[2], bh4[3]);
            mma16816(acc[0][2*jp],   ah[0],  bl4[0], bl4[1]);
            mma16816(acc[1][2*jp],   ah[1],  bl4[0], bl4[1]);
            mma16816(acc[0][2*jp+1], ah[0],  bl4[2], bl4[3]);
            mma16816(acc[1][2*jp+1], ah[1],  bl4[2], bl4[3]);
            mma16816(acc[0][2*jp],   al_[0], bh4[0], bh4[1]);
            mma16816(acc[1][2*jp],   al_[1], bh4[0], bh4[1]);
            mma16816(acc[0][2*jp+1], al_[0], bh4[2], bh4[3]);
            mma16816(acc[1][2*jp+1], al_[1], bh4[2], bh4[3]);
        }
        __syncthreads();
    }
}

// ---------------- fused QKV projection kernel ------------------------------
// grid (64, 18): blockIdx.y -> slot (0=Q,1=K,2=V) x 6 n-tiles
__global__ void __launch_bounds__(256)
gemm_qkv(const float* __restrict__ bq, const float* __restrict__ bk,
         const float* __restrict__ bv, float qscale)
{
    __shared__ __nv_bfloat16 smb[2][4][128][GPAD];
    const uint32_t sb = smem_u32(&smb[0][0][0][0]);
    const int tid  = threadIdx.x;
    const int lane = tid & 31;
    const int w    = tid >> 5;
    const int wm   = w & 3;
    const int wn   = w >> 2;
    const int m0   = blockIdx.x * 128;
    const int slot = blockIdx.y / 6;
    const int n0   = (blockIdx.y % 6) * 128;

    const __nv_bfloat16* Ah = (slot == 0) ? g_v1h : g_v2h;
    const __nv_bfloat16* Al = (slot == 0) ? g_v1l : g_v2l;
    const __nv_bfloat16* Wh = g_Wh + (size_t)slot * EMB * EMB;
    const __nv_bfloat16* Wl = g_Wl + (size_t)slot * EMB * EMB;
    const float* bias = (slot == 0) ? bq : (slot == 1) ? bk : bv;
    const float scale = (slot == 0) ? qscale : 1.f;
    __nv_bfloat16* dstH = (slot == 0) ? g_Qh : (slot == 1) ? g_Kh : g_Vh;
    __nv_bfloat16* dstL = (slot == 0) ? g_Ql : (slot == 1) ? g_Kl : g_Vl;

    float acc[2][8][4];
#pragma unroll
    for (int i = 0; i < 2; i++)
#pragma unroll
        for (int j = 0; j < 8; j++)
#pragma unroll
            for (int c = 0; c < 4; c++) acc[i][j][c] = 0.f;

    gemm_mainloop(Ah, Al, Wh, Wl, m0, n0, sb, tid, lane, wm, wn, acc);

    const int gid = lane >> 2, tig = lane & 3;
#pragma unroll
    for (int i = 0; i < 2; i++) {
#pragma unroll
        for (int j = 0; j < 8; j++) {
            int row = m0 + wm * 32 + i * 16 + gid;
            int col = n0 + wn * 64 + j * 8 + tig * 2;
            float b0 = bias[col], b1 = bias[col + 1];
#pragma unroll
            for (int hrow = 0; hrow < 2; hrow++) {
                int m = row + hrow * 8;
                float v0 = (acc[i][j][hrow * 2 + 0] + b0) * scale;
                float v1 = (acc[i][j][hrow * 2 + 1] + b1) * scale;
                uint32_t hi, lo;
                splitpair(v0, v1, hi, lo);
                int bi = m >> 11, si = m & 2047;
                int h = col >> 6, d = col & 63;
                size_t base = (((size_t)(bi * HEADS + h)) * SEQ + si) * DIM + d;
                *(uint32_t*)&dstH[base] = hi;
                *(uint32_t*)&dstL[base] = lo;
            }
        }
    }
}

// ---------------- output projection kernel ---------------------------------
__global__ void __launch_bounds__(256)
gemm_o(const float* __restrict__ bias, float* __restrict__ dstF,
       const float* __restrict__ alphaP, const float* __restrict__ betaP)
{
    __shared__ __nv_bfloat16 smb[2][4][128][GPAD];
    const uint32_t sb = smem_u32(&smb[0][0][0][0]);
    const int tid  = threadIdx.x;
    const int lane = tid & 31;
    const int w    = tid >> 5;
    const int wm   = w & 3;
    const int wn   = w >> 2;
    const int m0 = blockIdx.x * 128;
    const int n0 = blockIdx.y * 128;

    float acc[2][8][4];
#pragma unroll
    for (int i = 0; i < 2; i++)
#pragma unroll
        for (int j = 0; j < 8; j++)
#pragma unroll
            for (int c = 0; c < 4; c++) acc[i][j][c] = 0.f;

    gemm_mainloop(g_v1h, g_v1l,
                  g_Wh + (size_t)3 * EMB * EMB, g_Wl + (size_t)3 * EMB * EMB,
                  m0, n0, sb, tid, lane, wm, wn, acc);

    const int gid = lane >> 2, tig = lane & 3;
    const float al = *alphaP;
    const float be = *betaP;
#pragma unroll
    for (int i = 0; i < 2; i++) {
#pragma unroll
        for (int j = 0; j < 8; j++) {
            int row = m0 + wm * 32 + i * 16 + gid;
            int col = n0 + wn * 64 + j * 8 + tig * 2;
            float b0 = bias[col], b1 = bias[col + 1];
#pragma unroll
            for (int hrow = 0; hrow < 2; hrow++) {
                int m = row + hrow * 8;
                size_t r = (size_t)m * EMB + col;
                float2 ad = *(const float2*)&g_AO[r];
                float2 o;
                o.x = be * (acc[i][j][hrow * 2 + 0] + b0) + al * ad.x;
                o.y = be * (acc[i][j][hrow * 2 + 1] + b1) + al * ad.y;
                *(float2*)&dstF[r] = o;
            }
        }
    }
}

// ---------------- HMMA flash attention (cp.async 2-stage, KV tile 32) ------
#define KVT  32
#define APAD 72
#define ATEN (KVT*APAD)
#define ASTG (4*ATEN)

__global__ void __launch_bounds__(256) attn_mma()
{
    __shared__ __nv_bfloat16 kvs[2][4][KVT][APAD];
    const uint32_t sb = smem_u32(&kvs[0][0][0][0]);
    const int tid  = threadIdx.x;
    const int lane = tid & 31;
    const int w    = tid >> 5;
    const int gid  = lane >> 2, tig = lane & 3;
    const int bh = blockIdx.y;
    const int q0 = blockIdx.x * 128;

    const size_t bhoff = (size_t)bh * SEQ * DIM;
    const __nv_bfloat16* srcs[4] = {g_Kh + bhoff, g_Kl + bhoff, g_Vh + bhoff, g_Vl + bhoff};

    auto prefetch = [&](int kt, int st) {
#pragma unroll
        for (int u = 0; u < 4; u++) {
            int idx  = tid + u * 256;
            int tile = idx >> 8;
            int r    = (idx >> 3) & 31;
            int c8   = idx & 7;
            uint32_t dst = sb + (uint32_t)(st * ASTG + tile * ATEN + r * APAD + c8 * 8) * 2;
            CP_A16(dst, srcs[tile] + (size_t)(kt * KVT + r) * DIM + c8 * 8);
        }
        CP_COMMIT();
    };

    // Q fragments straight from gmem
    uint32_t qfh[4][4], qfl[4][4];
    {
        const int r0 = q0 + w * 16 + gid;
#pragma unroll
        for (int t = 0; t < 4; t++) {
            int kc = t * 16 + tig * 2;
            const __nv_bfloat16* ph_ = g_Qh + bhoff;
            const __nv_bfloat16* pl_ = g_Ql + bhoff;
            qfh[t][0] = *(const uint32_t*)(ph_ + (size_t)r0 * DIM + kc);
            qfh[t][1] = *(const uint32_t*)(ph_ + (size_t)(r0 + 8) * DIM + kc);
            qfh[t][2] = *(const uint32_t*)(ph_ + (size_t)r0 * DIM + kc + 8);
            qfh[t][3] = *(const uint32_t*)(ph_ + (size_t)(r0 + 8) * DIM + kc + 8);
            qfl[t][0] = *(const uint32_t*)(pl_ + (size_t)r0 * DIM + kc);
            qfl[t][1] = *(const uint32_t*)(pl_ + (size_t)(r0 + 8) * DIM + kc);
            qfl[t][2] = *(const uint32_t*)(pl_ + (size_t)r0 * DIM + kc + 8);
            qfl[t][3] = *(const uint32_t*)(pl_ + (size_t)(r0 + 8) * DIM + kc + 8);
        }
    }

    float m_[2] = {-1e30f, -1e30f};
    float l_[2] = {0.f, 0.f};
    float o[8][4];
#pragma unroll
    for (int j = 0; j < 8; j++)
#pragma unroll
        for (int c = 0; c < 4; c++) o[j][c] = 0.f;

    prefetch(0, 0);
    const int NT = SEQ / KVT;    // 64
    for (int kt = 0; kt < NT; kt++) {
        const int st = kt & 1;
        if (kt + 1 < NT) { prefetch(kt + 1, st ^ 1); CP_WAIT1(); }
        else             { CP_WAIT0(); }
        __syncthreads();
        const uint32_t so = sb + (uint32_t)(st * ASTG) * 2;

        // scores S[16 x 32] per warp — 4 independent accumulators per term
        float s[4][4];
#pragma unroll
        for (int j = 0; j < 4; j++)
#pragma unroll
            for (int c = 0; c < 4; c++) s[j][c] = 0.f;
#pragma unroll
        for (int t = 0; t < 4; t++) {
            int rowA = ((lane >> 4) << 3) + (lane & 7);
            int colh = t * 16 + (((lane >> 3) & 1) << 3);
            uint32_t ka[4], la[4], kb[4], lb[4];
            ldm_x4(ka, so + (uint32_t)(0 * ATEN + rowA * APAD + colh) * 2);
            ldm_x4(la, so + (uint32_t)(1 * ATEN + rowA * APAD + colh) * 2);
            ldm_x4(kb, so + (uint32_t)(0 * ATEN + (16 + rowA) * APAD + colh) * 2);
            ldm_x4(lb, so + (uint32_t)(1 * ATEN + (16 + rowA) * APAD + colh) * 2);
            mma16816(s[0], qfh[t], ka[0], ka[1]);
            mma16816(s[1], qfh[t], ka[2], ka[3]);
            mma16816(s[2], qfh[t], kb[0], kb[1]);
            mma16816(s[3], qfh[t], kb[2], kb[3]);
            mma16816(s[0], qfh[t], la[0], la[1]);
            mma16816(s[1], qfh[t], la[2], la[3]);
            mma16816(s[2], qfh[t], lb[0], lb[1]);
            mma16816(s[3], qfh[t], lb[2], lb[3]);
            mma16816(s[0], qfl[t], ka[0], ka[1]);
            mma16816(s[1], qfl[t], ka[2], ka[3]);
            mma16816(s[2], qfl[t], kb[0], kb[1]);
            mma16816(s[3], qfl[t], kb[2], kb[3]);
        }

        // online softmax (rows gid, gid+8)
        float rmax[2] = {-1e30f, -1e30f};
#pragma unroll
        for (int j = 0; j < 4; j++) {
            rmax[0] = fmaxf(rmax[0], fmaxf(s[j][0], s[j][1]));
            rmax[1] = fmaxf(rmax[1], fmaxf(s[j][2], s[j][3]));
        }
#pragma unroll
        for (int d = 1; d < 4; d <<= 1) {
            rmax[0] = fmaxf(rmax[0], __shfl_xor_sync(0xffffffffu, rmax[0], d));
            rmax[1] = fmaxf(rmax[1], __shfl_xor_sync(0xffffffffu, rmax[1], d));
        }
        float mnew[2], corr[2];
        mnew[0] = fmaxf(m_[0], rmax[0]);
        mnew[1] = fmaxf(m_[1], rmax[1]);
        corr[0] = __expf(m_[0] - mnew[0]);
        corr[1] = __expf(m_[1] - mnew[1]);
        float rsum[2] = {0.f, 0.f};
#pragma unroll
        for (int j = 0; j < 4; j++) {
            s[j][0] = __expf(s[j][0] - mnew[0]);
            s[j][1] = __expf(s[j][1] - mnew[0]);
            s[j][2] = __expf(s[j][2] - mnew[1]);
            s[j][3] = __expf(s[j][3] - mnew[1]);
            rsum[0] += s[j][0] + s[j][1];
            rsum[1] += s[j][2] + s[j][3];
        }
#pragma unroll
        for (int j = 0; j < 8; j++) {
            o[j][0] *= corr[0]; o[j][1] *= corr[0];
            o[j][2] *= corr[1]; o[j][3] *= corr[1];
        }
#pragma unroll
        for (int d = 1; d < 4; d <<= 1) {
            rsum[0] += __shfl_xor_sync(0xffffffffu, rsum[0], d);
            rsum[1] += __shfl_xor_sync(0xffffffffu, rsum[1], d);
        }
        l_[0] = l_[0] * corr[0] + rsum[0];
        l_[1] = l_[1] * corr[1] + rsum[1];
        m_[0] = mnew[0]; m_[1] = mnew[1];

        // P·V with 4-way interleaving
#pragma unroll
        for (int t = 0; t < 2; t++) {
            uint32_t ph[4], pl[4];
            splitpair(s[2*t][0],   s[2*t][1],   ph[0], pl[0]);
            splitpair(s[2*t][2],   s[2*t][3],   ph[1], pl[1]);
            splitpair(s[2*t+1][0], s[2*t+1][1], ph[2], pl[2]);
            splitpair(s[2*t+1][2], s[2*t+1][3], ph[3], pl[3]);
            int row = t * 16 + (((lane >> 3) & 1) << 3) + (lane & 7);
#pragma unroll
            for (int jq = 0; jq < 2; jq++) {
                int colA = (jq * 2) * 16 + ((lane >> 4) << 3);
                int colB = (jq * 2 + 1) * 16 + ((lane >> 4) << 3);
                uint32_t va[4], wa[4], vb[4], wb[4];
                ldm_x4t(va, so + (uint32_t)(2 * ATEN + row * APAD + colA) * 2);
                ldm_x4t(wa, so + (uint32_t)(3 * ATEN + row * APAD + colA) * 2);
                ldm_x4t(vb, so + (uint32_t)(2 * ATEN + row * APAD + colB) * 2);
                ldm_x4t(wb, so + (uint32_t)(3 * ATEN + row * APAD + colB) * 2);
                int a = jq * 4;
                mma16816(o[a+0], ph, va[0], va[1]);
                mma16816(o[a+1], ph, va[2], va[3]);
                mma16816(o[a+2], ph, vb[0], vb[1]);
                mma16816(o[a+3], ph, vb[2], vb[3]);
                mma16816(o[a+0], ph, wa[0], wa[1]);
                mma16816(o[a+1], ph, wa[2], wa[3]);
                mma16816(o[a+2], ph, wb[0], wb[1]);
                mma16816(o[a+3], ph, wb[2], wb[3]);
                mma16816(o[a+0], pl, va[0], va[1]);
                mma16816(o[a+1], pl, va[2], va[3]);
                mma16816(o[a+2], pl, vb[0], vb[1]);
                mma16816(o[a+3], pl, vb[2], vb[3]);
            }
        }
        __syncthreads();
    }

    // epilogue -> g_AO [b, s, h*64+d] fp32
    const int bi = bh / HEADS;
    const int h  = bh % HEADS;
    float inv0 = 1.f / l_[0];
    float inv1 = 1.f / l_[1];
#pragma unroll
    for (int j = 0; j < 8; j++) {
        int q = q0 + w * 16 + gid;
        int d = j * 8 + tig * 2;
        float2 v0 = make_float2(o[j][0] * inv0, o[j][1] * inv0);
        float2 v1 = make_float2(o[j][2] * inv1, o[j][3] * inv1);
        *(float2*)&g_AO[((size_t)(bi * SEQ + q)) * EMB + h * DIM + d] = v0;
        *(float2*)&g_AO[((size_t)(bi * SEQ + q + 8)) * EMB + h * DIM + d] = v1;
    }
}

// ---------------------------------------------------------------------------
extern "C" void kernel_launch(void* const* d_in, const int* in_sizes, int n_in,
                              void* d_out, int out_size)
{
    const float* v1    = (const float*)d_in[0];
    const float* v2    = (const float*)d_in[1];
    const float* Wq    = (const float*)d_in[2];
    const float* bq    = (const float*)d_in[3];
    const float* Wk    = (const float*)d_in[4];
    const float* bk    = (const float*)d_in[5];
    const float* Wv    = (const float*)d_in[6];
    const float* bv    = (const float*)d_in[7];
    const float* Wo    = (const float*)d_in[8];
    const float* bo    = (const float*)d_in[9];
    const float* alpha = (const float*)d_in[10];
    const float* beta  = (const float*)d_in[11];
    float* out = (float*)d_out;

    __nv_bfloat16 *v1h, *v1l, *v2h, *v2l, *Wh, *Wl;
    cudaGetSymbolAddress((void**)&v1h, g_v1h);
    cudaGetSymbolAddress((void**)&v1l, g_v1l);
    cudaGetSymbolAddress((void**)&v2h, g_v2h);
    cudaGetSymbolAddress((void**)&v2l, g_v2l);
    cudaGetSymbolAddress((void**)&Wh,  g_Wh);
    cudaGetSymbolAddress((void**)&Wl,  g_Wl);

    const int nAct4 = MROWS * EMB / 4;
    const int nW4   = EMB * EMB / 4;
    cvt_split<<<(nAct4 + 255) / 256, 256>>>(v1, v1h, v1l, nAct4);
    cvt_split<<<(nAct4 + 255) / 256, 256>>>(v2, v2h, v2l, nAct4);
    cvt_split_w<<<dim3((nW4 + 255) / 256, 4), 256>>>(Wq, Wk, Wv, Wo, Wh, Wl, nW4);

    const float qscale = 1.0f / sqrtf((float)EMB);

    gemm_qkv<<<dim3(MROWS / 128, 18), 256>>>(bq, bk, bv, qscale);

    attn_mma<<<dim3(SEQ / 128, BATCH * HEADS), 256>>>();

    gemm_o<<<dim3(MROWS / 128, EMB / 128), 256>>>(bo, out, alpha, beta);
}

// round 8
// speedup vs baseline: 2.7253x; 2.7253x over previous
#include <cuda_runtime.h>
#include <cuda_fp16.h>
#include <math.h>
#include <stdint.h>

#define HEADS 12
#define SEQ   2048
#define DIM   64
#define EMB   768
#define BATCH 4
#define MROWS (BATCH*SEQ)   // 8192
#define QSCALE 0.036084391824351615f   // 1/sqrt(768)

// ---------------- scratch (static device globals; no allocation) ----------
__device__ float g_AO[MROWS*EMB];            // attention out, [B*S, 768]

__device__ __half g_Q[BATCH*HEADS*SEQ*DIM];  // [B,H,S,D] fp16
__device__ __half g_K[BATCH*HEADS*SEQ*DIM];
__device__ __half g_V[BATCH*HEADS*SEQ*DIM];

__device__ __half g_v1[MROWS*EMB];
__device__ __half g_v2[MROWS*EMB];
__device__ __half g_W[4*EMB*EMB];            // slots: 0=q 1=k 2=v 3=o

// ---------------- helpers --------------------------------------------------
__device__ __forceinline__ uint32_t smem_u32(const void* p) {
    uint32_t a;
    asm("{ .reg .u64 t; cvta.to.shared.u64 t, %1; cvt.u32.u64 %0, t; }"
        : "=r"(a) : "l"(p));
    return a;
}
__device__ __forceinline__ void mma16816(float* c, const uint32_t* a,
                                         uint32_t b0, uint32_t b1) {
    asm volatile(
        "mma.sync.aligned.m16n8k16.row.col.f32.f16.f16.f32 "
        "{%0,%1,%2,%3}, {%4,%5,%6,%7}, {%8,%9}, {%0,%1,%2,%3};"
        : "+f"(c[0]), "+f"(c[1]), "+f"(c[2]), "+f"(c[3])
        : "r"(a[0]), "r"(a[1]), "r"(a[2]), "r"(a[3]), "r"(b0), "r"(b1));
}
__device__ __forceinline__ void ldm_x4(uint32_t* r, uint32_t addr) {
    asm volatile("ldmatrix.sync.aligned.m8n8.x4.shared.b16 {%0,%1,%2,%3}, [%4];"
                 : "=r"(r[0]), "=r"(r[1]), "=r"(r[2]), "=r"(r[3]) : "r"(addr));
}
__device__ __forceinline__ void ldm_x4t(uint32_t* r, uint32_t addr) {
    asm volatile("ldmatrix.sync.aligned.m8n8.x4.trans.shared.b16 {%0,%1,%2,%3}, [%4];"
                 : "=r"(r[0]), "=r"(r[1]), "=r"(r[2]), "=r"(r[3]) : "r"(addr));
}
#define CP_A16(dst, src) \
    asm volatile("cp.async.cg.shared.global [%0], [%1], 16;" :: "r"(dst), "l"(src))
#define CP_COMMIT() asm volatile("cp.async.commit_group;" ::: "memory")
#define CP_WAIT1()  asm volatile("cp.async.wait_group 1;" ::: "memory")
#define CP_WAIT0()  asm volatile("cp.async.wait_group 0;" ::: "memory")

__device__ __forceinline__ uint32_t packh(float a, float b) {
    __half2 t = __floats2half2_rn(a, b);
    return *(uint32_t*)&t;
}

// ---------------- fp16 conversion ------------------------------------------
__global__ void __launch_bounds__(256)
cvt_h(const float* __restrict__ in, __half* __restrict__ out, int n4)
{
    int i = blockIdx.x * blockDim.x + threadIdx.x;
    if (i >= n4) return;
    float4 v = ((const float4*)in)[i];
    ((uint2*)out)[i] = make_uint2(packh(v.x, v.y), packh(v.z, v.w));
}
__global__ void __launch_bounds__(256)
cvt_h_w(const float* __restrict__ w0, const float* __restrict__ w1,
        const float* __restrict__ w2, const float* __restrict__ w3,
        __half* __restrict__ out, int n4)
{
    int i = blockIdx.x * blockDim.x + threadIdx.x;
    if (i >= n4) return;
    int s = blockIdx.y;
    const float* in = (s == 0) ? w0 : (s == 1) ? w1 : (s == 2) ? w2 : w3;
    float4 v = ((const float4*)in)[i];
    ((uint2*)out)[(size_t)s * (EMB * EMB / 4) + i] =
        make_uint2(packh(v.x, v.y), packh(v.z, v.w));
}

// ---------------- shared GEMM mainloop (cp.async 2-stage, K-tile 32) -------
#define GKT  32
#define GPAD 40
#define GTEN (128*GPAD)
#define GSTG (2*GTEN)

__device__ __forceinline__ void gemm_mainloop(
    const __half* __restrict__ A, const __half* __restrict__ W,
    int m0, int n0, uint32_t sb, int tid, int lane, int wm, int wn,
    float (&acc)[2][8][4])
{
    const __half* srcs[2] = {A, W};
    const int rb[2] = {m0, n0};

    auto prefetch = [&](int kt, int st) {
#pragma unroll
        for (int u = 0; u < 4; u++) {
            int idx  = tid + u * 256;
            int tile = idx >> 9;
            int r    = (idx >> 2) & 127;
            int c    = idx & 3;
            uint32_t dst = sb + (uint32_t)(st * GSTG + tile * GTEN + r * GPAD + c * 8) * 2;
            CP_A16(dst, srcs[tile] + (size_t)(rb[tile] + r) * EMB + kt * GKT + c * 8);
        }
        CP_COMMIT();
    };

    prefetch(0, 0);
    const int NKT = EMB / GKT;   // 24
    for (int kt = 0; kt < NKT; kt++) {
        const int st = kt & 1;
        if (kt + 1 < NKT) { prefetch(kt + 1, st ^ 1); CP_WAIT1(); }
        else              { CP_WAIT0(); }
        __syncthreads();

        const uint32_t so = sb + (uint32_t)(st * GSTG) * 2;
        uint32_t af[2][2][4];
#pragma unroll
        for (int i = 0; i < 2; i++)
#pragma unroll
            for (int t = 0; t < 2; t++) {
                int row  = wm * 32 + i * 16 + (lane & 15);
                int colh = t * 16 + ((lane >> 4) << 3);
                ldm_x4(af[i][t], so + (uint32_t)(0 * GTEN + row * GPAD + colh) * 2);
            }
#pragma unroll
        for (int jp = 0; jp < 4; jp++) {
            int row = wn * 64 + jp * 16 + ((lane >> 4) << 3) + (lane & 7);
#pragma unroll
            for (int t = 0; t < 2; t++) {
                int colh = t * 16 + (((lane >> 3) & 1) << 3);
                uint32_t bf[4];
                ldm_x4(bf, so + (uint32_t)(1 * GTEN + row * GPAD + colh) * 2);
                mma16816(acc[0][2*jp],   af[0][t], bf[0], bf[1]);
                mma16816(acc[1][2*jp],   af[1][t], bf[0], bf[1]);
                mma16816(acc[0][2*jp+1], af[0][t], bf[2], bf[3]);
                mma16816(acc[1][2*jp+1], af[1][t], bf[2], bf[3]);
            }
        }
        __syncthreads();
    }
}

// ---------------- fused QKV projection kernel ------------------------------
// grid (64, 18): blockIdx.y -> slot (0=Q,1=K,2=V) x 6 n-tiles
__global__ void __launch_bounds__(256, 2)
gemm_qkv(const float* __restrict__ bq, const float* __restrict__ bk,
         const float* __restrict__ bv)
{
    __shared__ __half smb[2][2][128][GPAD];
    const uint32_t sb = smem_u32(&smb[0][0][0][0]);
    const int tid  = threadIdx.x;
    const int lane = tid & 31;
    const int w    = tid >> 5;
    const int wm   = w & 3;
    const int wn   = w >> 2;
    const int m0   = blockIdx.x * 128;
    const int slot = blockIdx.y / 6;
    const int n0   = (blockIdx.y % 6) * 128;

    const __half* A = (slot == 0) ? g_v1 : g_v2;
    const __half* W = g_W + (size_t)slot * EMB * EMB;
    const float* bias = (slot == 0) ? bq : (slot == 1) ? bk : bv;
    __half* dst = (slot == 0) ? g_Q : (slot == 1) ? g_K : g_V;

    float acc[2][8][4];
#pragma unroll
    for (int i = 0; i < 2; i++)
#pragma unroll
        for (int j = 0; j < 8; j++)
#pragma unroll
            for (int c = 0; c < 4; c++) acc[i][j][c] = 0.f;

    gemm_mainloop(A, W, m0, n0, sb, tid, lane, wm, wn, acc);

    const int gid = lane >> 2, tig = lane & 3;
#pragma unroll
    for (int i = 0; i < 2; i++) {
#pragma unroll
        for (int j = 0; j < 8; j++) {
            int row = m0 + wm * 32 + i * 16 + gid;
            int col = n0 + wn * 64 + j * 8 + tig * 2;
            float b0 = bias[col], b1 = bias[col + 1];
#pragma unroll
            for (int hrow = 0; hrow < 2; hrow++) {
                int m = row + hrow * 8;
                float v0 = acc[i][j][hrow * 2 + 0] + b0;
                float v1 = acc[i][j][hrow * 2 + 1] + b1;
                int bi = m >> 11, si = m & 2047;
                int h = col >> 6, d = col & 63;
                size_t base = (((size_t)(bi * HEADS + h)) * SEQ + si) * DIM + d;
                *(uint32_t*)&dst[base] = packh(v0, v1);
            }
        }
    }
}

// ---------------- output projection kernel ---------------------------------
__global__ void __launch_bounds__(256, 2)
gemm_o(const float* __restrict__ bias, float* __restrict__ dstF,
       const float* __restrict__ alphaP, const float* __restrict__ betaP)
{
    __shared__ __half smb[2][2][128][GPAD];
    const uint32_t sb = smem_u32(&smb[0][0][0][0]);
    const int tid  = threadIdx.x;
    const int lane = tid & 31;
    const int w    = tid >> 5;
    const int wm   = w & 3;
    const int wn   = w >> 2;
    const int m0 = blockIdx.x * 128;
    const int n0 = blockIdx.y * 128;

    float acc[2][8][4];
#pragma unroll
    for (int i = 0; i < 2; i++)
#pragma unroll
        for (int j = 0; j < 8; j++)
#pragma unroll
            for (int c = 0; c < 4; c++) acc[i][j][c] = 0.f;

    gemm_mainloop(g_v1, g_W + (size_t)3 * EMB * EMB,
                  m0, n0, sb, tid, lane, wm, wn, acc);

    const int gid = lane >> 2, tig = lane & 3;
    const float al = *alphaP;
    const float be = *betaP;
#pragma unroll
    for (int i = 0; i < 2; i++) {
#pragma unroll
        for (int j = 0; j < 8; j++) {
            int row = m0 + wm * 32 + i * 16 + gid;
            int col = n0 + wn * 64 + j * 8 + tig * 2;
            float b0 = bias[col], b1 = bias[col + 1];
#pragma unroll
            for (int hrow = 0; hrow < 2; hrow++) {
                int m = row + hrow * 8;
                size_t r = (size_t)m * EMB + col;
                float2 ad = *(const float2*)&g_AO[r];
                float2 o;
                o.x = be * (acc[i][j][hrow * 2 + 0] + b0) + al * ad.x;
                o.y = be * (acc[i][j][hrow * 2 + 1] + b1) + al * ad.y;
                *(float2*)&dstF[r] = o;
            }
        }
    }
}

// ---------------- HMMA flash attention (cp.async 2-stage, KV tile 64) ------
#define KVT  64
#define APAD 72
#define ATEN (KVT*APAD)
#define ASTG (2*ATEN)

__global__ void __launch_bounds__(256, 2) attn_mma()
{
    __shared__ __half kvs[2][2][KVT][APAD];   // [stage][K=0/V=1][row][col]
    const uint32_t sb = smem_u32(&kvs[0][0][0][0]);
    const int tid  = threadIdx.x;
    const int lane = tid & 31;
    const int w    = tid >> 5;
    const int gid  = lane >> 2, tig = lane & 3;
    const int bh = blockIdx.y;
    const int q0 = blockIdx.x * 128;

    const size_t bhoff = (size_t)bh * SEQ * DIM;
    const __half* srcs[2] = {g_K + bhoff, g_V + bhoff};

    auto prefetch = [&](int kt, int st) {
#pragma unroll
        for (int u = 0; u < 4; u++) {
            int idx  = tid + u * 256;
            int tile = idx >> 9;
            int r    = (idx >> 3) & 63;
            int c8   = idx & 7;
            uint32_t dst = sb + (uint32_t)(st * ASTG + tile * ATEN + r * APAD + c8 * 8) * 2;
            CP_A16(dst, srcs[tile] + (size_t)(kt * KVT + r) * DIM + c8 * 8);
        }
        CP_COMMIT();
    };

    // Q fragments straight from gmem
    uint32_t qf[4][4];
    {
        const int r0 = q0 + w * 16 + gid;
        const __half* p = g_Q + bhoff;
#pragma unroll
        for (int t = 0; t < 4; t++) {
            int kc = t * 16 + tig * 2;
            qf[t][0] = *(const uint32_t*)(p + (size_t)r0 * DIM + kc);
            qf[t][1] = *(const uint32_t*)(p + (size_t)(r0 + 8) * DIM + kc);
            qf[t][2] = *(const uint32_t*)(p + (size_t)r0 * DIM + kc + 8);
            qf[t][3] = *(const uint32_t*)(p + (size_t)(r0 + 8) * DIM + kc + 8);
        }
    }

    float m_[2] = {-1e30f, -1e30f};
    float l_[2] = {0.f, 0.f};
    float o[8][4];
#pragma unroll
    for (int j = 0; j < 8; j++)
#pragma unroll
        for (int c = 0; c < 4; c++) o[j][c] = 0.f;

    prefetch(0, 0);
    const int NT = SEQ / KVT;    // 32
    for (int kt = 0; kt < NT; kt++) {
        const int st = kt & 1;
        if (kt + 1 < NT) { prefetch(kt + 1, st ^ 1); CP_WAIT1(); }
        else             { CP_WAIT0(); }
        __syncthreads();
        const uint32_t so = sb + (uint32_t)(st * ASTG) * 2;

        // scores S[16 x 64] per warp
        float s[8][4];
#pragma unroll
        for (int j = 0; j < 8; j++)
#pragma unroll
            for (int c = 0; c < 4; c++) s[j][c] = 0.f;
#pragma unroll
        for (int jp = 0; jp < 4; jp++) {
            int row = jp * 16 + ((lane >> 4) << 3) + (lane & 7);
#pragma unroll
            for (int t = 0; t < 4; t++) {
                int colh = t * 16 + (((lane >> 3) & 1) << 3);
                uint32_t kf[4];
                ldm_x4(kf, so + (uint32_t)(0 * ATEN + row * APAD + colh) * 2);
                mma16816(s[2*jp],   qf[t], kf[0], kf[1]);
                mma16816(s[2*jp+1], qf[t], kf[2], kf[3]);
            }
        }
        // scale scores by 1/sqrt(768)
#pragma unroll
        for (int j = 0; j < 8; j++)
#pragma unroll
            for (int c = 0; c < 4; c++) s[j][c] *= QSCALE;

        // online softmax (rows gid, gid+8)
        float rmax[2] = {-1e30f, -1e30f};
#pragma unroll
        for (int j = 0; j < 8; j++) {
            rmax[0] = fmaxf(rmax[0], fmaxf(s[j][0], s[j][1]));
            rmax[1] = fmaxf(rmax[1], fmaxf(s[j][2], s[j][3]));
        }
#pragma unroll
        for (int d = 1; d < 4; d <<= 1) {
            rmax[0] = fmaxf(rmax[0], __shfl_xor_sync(0xffffffffu, rmax[0], d));
            rmax[1] = fmaxf(rmax[1], __shfl_xor_sync(0xffffffffu, rmax[1], d));
        }
        float mnew[2], corr[2];
        mnew[0] = fmaxf(m_[0], rmax[0]);
        mnew[1] = fmaxf(m_[1], rmax[1]);
        corr[0] = __expf(m_[0] - mnew[0]);
        corr[1] = __expf(m_[1] - mnew[1]);
        float rsum[2] = {0.f, 0.f};
#pragma unroll
        for (int j = 0; j < 8; j++) {
            s[j][0] = __expf(s[j][0] - mnew[0]);
            s[j][1] = __expf(s[j][1] - mnew[0]);
            s[j][2] = __expf(s[j][2] - mnew[1]);
            s[j][3] = __expf(s[j][3] - mnew[1]);
            rsum[0] += s[j][0] + s[j][1];
            rsum[1] += s[j][2] + s[j][3];
            o[j][0] *= corr[0]; o[j][1] *= corr[0];
            o[j][2] *= corr[1]; o[j][3] *= corr[1];
        }
#pragma unroll
        for (int d = 1; d < 4; d <<= 1) {
            rsum[0] += __shfl_xor_sync(0xffffffffu, rsum[0], d);
            rsum[1] += __shfl_xor_sync(0xffffffffu, rsum[1], d);
        }
        l_[0] = l_[0] * corr[0] + rsum[0];
        l_[1] = l_[1] * corr[1] + rsum[1];
        m_[0] = mnew[0]; m_[1] = mnew[1];

        // P·V
#pragma unroll
        for (int t = 0; t < 4; t++) {
            uint32_t ph[4];
            ph[0] = packh(s[2*t][0],   s[2*t][1]);
            ph[1] = packh(s[2*t][2],   s[2*t][3]);
            ph[2] = packh(s[2*t+1][0], s[2*t+1][1]);
            ph[3] = packh(s[2*t+1][2], s[2*t+1][3]);
            int row = t * 16 + (((lane >> 3) & 1) << 3) + (lane & 7);
#pragma unroll
            for (int jq = 0; jq < 4; jq++) {
                int col = jq * 16 + ((lane >> 4) << 3);
                uint32_t vf[4];
                ldm_x4t(vf, so + (uint32_t)(1 * ATEN + row * APAD + col) * 2);
                mma16816(o[2*jq],   ph, vf[0], vf[1]);
                mma16816(o[2*jq+1], ph, vf[2], vf[3]);
            }
        }
        __syncthreads();
    }

    // epilogue -> g_AO [b, s, h*64+d] fp32
    const int bi = bh / HEADS;
    const int h  = bh % HEADS;
    float inv0 = 1.f / l_[0];
    float inv1 = 1.f / l_[1];
#pragma unroll
    for (int j = 0; j < 8; j++) {
        int q = q0 + w * 16 + gid;
        int d = j * 8 + tig * 2;
        float2 v0 = make_float2(o[j][0] * inv0, o[j][1] * inv0);
        float2 v1 = make_float2(o[j][2] * inv1, o[j][3] * inv1);
        *(float2*)&g_AO[((size_t)(bi * SEQ + q)) * EMB + h * DIM + d] = v0;
        *(float2*)&g_AO[((size_t)(bi * SEQ + q + 8)) * EMB + h * DIM + d] = v1;
    }
}

// ---------------------------------------------------------------------------
extern "C" void kernel_launch(void* const* d_in, const int* in_sizes, int n_in,
                              void* d_out, int out_size)
{
    const float* v1    = (const float*)d_in[0];
    const float* v2    = (const float*)d_in[1];
    const float* Wq    = (const float*)d_in[2];
    const float* bq    = (const float*)d_in[3];
    const float* Wk    = (const float*)d_in[4];
    const float* bk    = (const float*)d_in[5];
    const float* Wv    = (const float*)d_in[6];
    const float* bv    = (const float*)d_in[7];
    const float* Wo    = (const float*)d_in[8];
    const float* bo    = (const float*)d_in[9];
    const float* alpha = (const float*)d_in[10];
    const float* beta  = (const float*)d_in[11];
    float* out = (float*)d_out;

    __half *v1p, *v2p, *Wp;
    cudaGetSymbolAddress((void**)&v1p, g_v1);
    cudaGetSymbolAddress((void**)&v2p, g_v2);
    cudaGetSymbolAddress((void**)&Wp,  g_W);

    const int nAct4 = MROWS * EMB / 4;
    const int nW4   = EMB * EMB / 4;
    cvt_h<<<(nAct4 + 255) / 256, 256>>>(v1, v1p, nAct4);
    cvt_h<<<(nAct4 + 255) / 256, 256>>>(v2, v2p, nAct4);
    cvt_h_w<<<dim3((nW4 + 255) / 256, 4), 256>>>(Wq, Wk, Wv, Wo, Wp, nW4);

    gemm_qkv<<<dim3(MROWS / 128, 18), 256>>>(bq, bk, bv);

    attn_mma<<<dim3(SEQ / 128, BATCH * HEADS), 256>>>();

    gemm_o<<<dim3(MROWS / 128, EMB / 128), 256>>>(bo, out, alpha, beta);
}